// round 14
// baseline (speedup 1.0000x reference)
#include <cuda_runtime.h>
#include <cuda_bf16.h>
#include <math.h>
#include <stdint.h>

#define HDIM 256
#define NMAX 50176
#define EMAX 800032
#define LMAX 8

// ---------------- scratch (static device globals; no allocation) ----------------
__device__ float g_h0 [(size_t)NMAX * HDIM];
__device__ float g_h1 [(size_t)NMAX * HDIM];
__device__ float g_m  [(size_t)NMAX * HDIM];
__device__ float g_wt [(size_t)LMAX * HDIM * HDIM];
__device__ int   g_rowptr[NMAX + 1];
__device__ int   g_fill[NMAX];
__device__ int   g_cnt [NMAX];
__device__ int   g_bsum[256];
__device__ int   g_boff[256];
__device__ int   g_col [EMAX];
__device__ float g_ewS [EMAX];
__device__ int   g_is64;
// bf16 split buffers: layout [rows x 512] = [hi(256) | lo(256)]
__device__ __nv_bfloat16 g_hsA[(size_t)NMAX * 512];
__device__ __nv_bfloat16 g_hsB[(size_t)NMAX * 512];
__device__ __nv_bfloat16 g_as [(size_t)NMAX * 512];
__device__ __nv_bfloat16 g_wts[(size_t)LMAX * HDIM * 512];
__device__ __nv_bfloat16 g_wgp[(size_t)2 * 3 * HDIM * 512];  // gate-permuted [w_ih | w_hh]

// ---------------- small PTX helpers (baseline ISA only) -------------------------
__device__ __forceinline__ uint32_t s2u(const void* p) {
    uint32_t a;
    asm("{ .reg .u64 t; cvta.to.shared.u64 t, %1; cvt.u32.u64 %0, t; }" : "=r"(a) : "l"(p));
    return a;
}
__device__ __forceinline__ uint32_t sw128(uint32_t off) { return off ^ ((off >> 3) & 0x70); }
__device__ __forceinline__ void cp16(uint32_t saddr, const void* g) {
    asm volatile("cp.async.cg.shared.global [%0], [%1], 16;" :: "r"(saddr), "l"(g) : "memory");
}
__device__ __forceinline__ void cp_commit() { asm volatile("cp.async.commit_group;" ::: "memory"); }
__device__ __forceinline__ void cp_wait0()  { asm volatile("cp.async.wait_group 0;" ::: "memory"); }
__device__ __forceinline__ void cp_wait1()  { asm volatile("cp.async.wait_group 1;" ::: "memory"); }
__device__ __forceinline__ void ldm_x4(uint32_t* r, uint32_t addr) {
    asm volatile("ldmatrix.sync.aligned.m8n8.x4.shared.b16 {%0,%1,%2,%3}, [%4];"
                 : "=r"(r[0]), "=r"(r[1]), "=r"(r[2]), "=r"(r[3]) : "r"(addr));
}
__device__ __forceinline__ void mma16816(float* d, const uint32_t* a, uint32_t b0, uint32_t b1) {
    asm volatile(
        "mma.sync.aligned.m16n8k16.row.col.f32.bf16.bf16.f32 "
        "{%0,%1,%2,%3}, {%4,%5,%6,%7}, {%8,%9}, {%0,%1,%2,%3};"
        : "+f"(d[0]), "+f"(d[1]), "+f"(d[2]), "+f"(d[3])
        : "r"(a[0]), "r"(a[1]), "r"(a[2]), "r"(a[3]), "r"(b0), "r"(b1));
}

// ---------------- edge-index dtype detection (int64 vs int32) -------------------
__global__ void detect_k(const unsigned int* p, int E) {
    __shared__ int any;
    if (threadIdx.x == 0) any = 0;
    __syncthreads();
    int acc = 0;
    int nchk = 2048;
    for (int i = threadIdx.x; i < nchk; i += blockDim.x)
        acc |= (int)p[2 * i + 1];
    if (acc) atomicOr(&any, 1);
    __syncthreads();
    if (threadIdx.x == 0) g_is64 = (any == 0) ? 1 : 0;
}

__device__ __forceinline__ int eidx(const void* p, long long pos) {
    if (g_is64) return (int)((const long long*)p)[pos];
    return ((const int*)p)[pos];
}

// ---------------- CSR build ------------------------------------------------------
__global__ void count_k(const void* ei, int E) {
    int i = blockIdx.x * blockDim.x + threadIdx.x;
    if (i < E) atomicAdd(&g_cnt[eidx(ei, (long long)E + i)], 1);
}

__global__ void scanA_k(int n) {
    __shared__ int sh[256];
    int t = threadIdx.x;
    int i = blockIdx.x * 256 + t;
    int v = (i < n) ? g_cnt[i] : 0;
    sh[t] = v;
    __syncthreads();
    #pragma unroll
    for (int off = 1; off < 256; off <<= 1) {
        int tv = (t >= off) ? sh[t - off] : 0;
        __syncthreads();
        sh[t] += tv;
        __syncthreads();
    }
    if (i < n) g_rowptr[i] = sh[t] - v;
    if (t == 255) g_bsum[blockIdx.x] = sh[255];
}
__global__ void scanB_k(int nb) {
    __shared__ int sh[256];
    int t = threadIdx.x;
    int v = (t < nb) ? g_bsum[t] : 0;
    sh[t] = v;
    __syncthreads();
    #pragma unroll
    for (int off = 1; off < 256; off <<= 1) {
        int tv = (t >= off) ? sh[t - off] : 0;
        __syncthreads();
        sh[t] += tv;
        __syncthreads();
    }
    g_boff[t] = sh[t] - v;
}
__global__ void scanC_k(int n, int E) {
    int i = blockIdx.x * 256 + threadIdx.x;
    if (i < n) {
        int r = g_rowptr[i] + g_boff[blockIdx.x];
        g_rowptr[i] = r;
        g_fill[i]   = r;
    }
    if (i == 0) g_rowptr[n] = E;
}

__global__ void scatter_k(const void* ei, const float* __restrict__ ew, int E) {
    int i = blockIdx.x * blockDim.x + threadIdx.x;
    if (i >= E) return;
    int d = eidx(ei, (long long)E + i);
    int s = eidx(ei, i);
    int pos = atomicAdd(&g_fill[d], 1);
    g_col[pos] = s;
    g_ewS[pos] = ew[i];
}

// ---------------- weight transpose: w[l][k][j] -> wt[l][j][k] --------------------
__global__ void transpose_k(const float* __restrict__ w, float* __restrict__ wt) {
    __shared__ float t[32][33];
    int l = blockIdx.z;
    int j0 = blockIdx.x * 32, k0 = blockIdx.y * 32;
    const float* wl  = w  + (size_t)l * HDIM * HDIM;
    float*       wtl = wt + (size_t)l * HDIM * HDIM;
    int tx = threadIdx.x, ty = threadIdx.y;
    t[ty][tx] = wl[(size_t)(k0 + ty) * HDIM + (j0 + tx)];
    __syncthreads();
    wtl[(size_t)(j0 + ty) * HDIM + (k0 + tx)] = t[tx][ty];
}

// ---------------- fp32 -> bf16 (hi|lo) split helpers -----------------------------
__device__ __forceinline__ void split4(float4 v, __nv_bfloat162* oh, __nv_bfloat162* ol) {
    __nv_bfloat16 hx = __float2bfloat16(v.x);
    __nv_bfloat16 hy = __float2bfloat16(v.y);
    __nv_bfloat16 hz = __float2bfloat16(v.z);
    __nv_bfloat16 hw = __float2bfloat16(v.w);
    oh[0] = __halves2bfloat162(hx, hy);
    oh[1] = __halves2bfloat162(hz, hw);
    ol[0] = __halves2bfloat162(__float2bfloat16(v.x - __bfloat162float(hx)),
                               __float2bfloat16(v.y - __bfloat162float(hy)));
    ol[1] = __halves2bfloat162(__float2bfloat16(v.z - __bfloat162float(hz)),
                               __float2bfloat16(v.w - __bfloat162float(hw)));
}

__global__ void split_k(const float* __restrict__ in, __nv_bfloat16* __restrict__ out, int rows) {
    int idx = blockIdx.x * blockDim.x + threadIdx.x;
    int total = rows * 64;
    if (idx >= total) return;
    int r = idx >> 6, c4 = idx & 63;
    float4 v = ((const float4*)(in + (size_t)r * HDIM))[c4];
    split4(v, (__nv_bfloat162*)(out + (size_t)r * 512 + c4 * 4),
              (__nv_bfloat162*)(out + (size_t)r * 512 + 256 + c4 * 4));
}

// gate-permuted split: out row p <- in row (gate*256 + group*8 + cl),
// p = group*24 + gate*8 + cl
__global__ void permsplit_k(const float* __restrict__ in, __nv_bfloat16* __restrict__ out) {
    int idx = blockIdx.x * blockDim.x + threadIdx.x;   // 768*64
    if (idx >= 768 * 64) return;
    int p = idx >> 6, c4 = idx & 63;
    int group = p / 24, rem = p % 24;
    int gate = rem >> 3, cl = rem & 7;
    int orig = gate * 256 + group * 8 + cl;
    float4 v = ((const float4*)(in + (size_t)orig * HDIM))[c4];
    split4(v, (__nv_bfloat162*)(out + (size_t)p * 512 + c4 * 4),
              (__nv_bfloat162*)(out + (size_t)p * 512 + 256 + c4 * 4));
}

// ---------------- panel source offsets (12 K-panels of 64) -----------------------
__device__ __forceinline__ int a_srcoff(int p) {
    return (p < 4) ? p * 64 : (p < 8) ? 256 + (p - 4) * 64 : (p - 8) * 64;
}
__device__ __forceinline__ int b_srcoff(int p) {
    return (p < 8) ? (p & 3) * 64 : 256 + (p - 8) * 64;
}

// ---------------- generic warp-mma GEMM (m = h @ W), tile 128x128 ---------------
#define GEMM_SMEM 98304

__global__ void __launch_bounds__(256, 2)
gemm_mma(const __nv_bfloat16* __restrict__ A, const __nv_bfloat16* __restrict__ B,
         float* __restrict__ C, int M, int Ntot) {
    extern __shared__ char smem[];
    uint32_t sb = s2u(smem);
    int tid = threadIdx.x, wid = tid >> 5, lane = tid & 31;
    int bm = blockIdx.x * 128, bn = blockIdx.y * 128;
    int wm = (wid & 3) * 32;
    int wn = (wid >> 2) * 64;

    float d[2][8][4];
    #pragma unroll
    for (int i = 0; i < 2; i++)
        #pragma unroll
        for (int j = 0; j < 8; j++)
            #pragma unroll
            for (int q = 0; q < 4; q++) d[i][j][q] = 0.f;

    int lrow = tid >> 1;
    int lseg = (tid & 1) * 64;
    auto load_panel = [&](int buf, int p) {
        uint32_t ab = sb + (uint32_t)buf * 32768u;
        uint32_t bb = ab + 16384u;
        int arow = bm + lrow; if (arow >= M) arow = M - 1;
        const __nv_bfloat16* asrc = A + (size_t)arow * 512 + a_srcoff(p) + (lseg >> 1);
        const __nv_bfloat16* bsrc = B + (size_t)(bn + lrow) * 512 + b_srcoff(p) + (lseg >> 1);
        #pragma unroll
        for (int j = 0; j < 4; j++) {
            cp16(ab + sw128((uint32_t)lrow * 128 + lseg + j * 16), asrc + j * 8);
            cp16(bb + sw128((uint32_t)lrow * 128 + lseg + j * 16), bsrc + j * 8);
        }
    };

    load_panel(0, 0); cp_commit();
    load_panel(1, 1); cp_commit();

    for (int p = 0; p < 12; p++) {
        if (p == 11) cp_wait0(); else cp_wait1();
        __syncthreads();
        if (p + 2 < 12) { load_panel((p + 2) % 3, p + 2); cp_commit(); }
        uint32_t ab = sb + (uint32_t)(p % 3) * 32768u;
        uint32_t bb = ab + 16384u;
        #pragma unroll
        for (int ks = 0; ks < 4; ks++) {
            uint32_t a[2][4];
            #pragma unroll
            for (int im = 0; im < 2; im++) {
                uint32_t r  = wm + im * 16 + (lane & 15);
                uint32_t cb = ks * 32 + ((lane >> 4) << 4);
                ldm_x4(a[im], ab + sw128(r * 128 + cb));
            }
            uint32_t b[4][4];
            #pragma unroll
            for (int ib = 0; ib < 4; ib++) {
                uint32_t r  = wn + ib * 16 + ((lane >> 4) << 3) + (lane & 7);
                uint32_t cb = ks * 32 + (((lane >> 3) & 1) << 4);
                ldm_x4(b[ib], bb + sw128(r * 128 + cb));
            }
            #pragma unroll
            for (int im = 0; im < 2; im++)
                #pragma unroll
                for (int in8 = 0; in8 < 8; in8++)
                    mma16816(d[im][in8], a[im], b[in8 >> 1][(in8 & 1) * 2],
                             b[in8 >> 1][(in8 & 1) * 2 + 1]);
        }
        __syncthreads();
    }

    #pragma unroll
    for (int in8 = 0; in8 < 8; in8++) {
        int col = bn + wn + in8 * 8 + (lane & 3) * 2;
        #pragma unroll
        for (int im = 0; im < 2; im++) {
            int r0 = bm + wm + im * 16 + (lane >> 2);
            if (r0 < M)
                *(float2*)(C + (size_t)r0 * Ntot + col) =
                    make_float2(d[im][in8][0], d[im][in8][1]);
            int r1 = r0 + 8;
            if (r1 < M)
                *(float2*)(C + (size_t)r1 * Ntot + col) =
                    make_float2(d[im][in8][2], d[im][in8][3]);
        }
    }
}

// ------------ fused dual-GEMM + GRU: tile 128x96 over gate-permuted cols --------
// Sweep 0 (panels 0-11):  A=as (agg split), B=w_ih permuted
// Sweep 1 (panels 12-23): A=hs (h split),   B=w_hh permuted
// r,z gates accumulate gi+gh in-place; n gate kept separate per sweep.
// Epilogue computes the GRU cell and writes hn (fp32) + hs_out (bf16 hi/lo).
#define FUSE_SMEM 86016   // 3 stages x (A 16KB + B 12KB)

__global__ void __launch_bounds__(256, 2)
gemm_gru(const __nv_bfloat16* __restrict__ Aas, const __nv_bfloat16* __restrict__ Ahs,
         const __nv_bfloat16* __restrict__ Wp,   // [w_ih_p | w_hh_p], each 768x512
         const float* __restrict__ b_ih, const float* __restrict__ b_hh,
         const float* __restrict__ h, float* __restrict__ hn,
         __nv_bfloat16* __restrict__ hs_out, int M) {
    extern __shared__ char smem[];
    uint32_t sb = s2u(smem);
    int tid = threadIdx.x, wid = tid >> 5, lane = tid & 31;
    int bm = blockIdx.x * 128, bn = blockIdx.y * 96;
    int wm = (wid & 3) * 32;
    int wn = (wid >> 2) * 48;

    // d[set][im][g][q]: set 0=r(gi+gh), 1=z(gi+gh), 2=n_gi, 3=n_gh
    float d[4][2][2][4];
    #pragma unroll
    for (int s = 0; s < 4; s++)
        #pragma unroll
        for (int i = 0; i < 2; i++)
            #pragma unroll
            for (int g = 0; g < 2; g++)
                #pragma unroll
                for (int q = 0; q < 4; q++) d[s][i][g][q] = 0.f;

    int lrow = tid >> 1;
    int lseg = (tid & 1) * 64;
    auto load_panel = [&](int buf, int qq) {
        int p = qq % 12;
        const __nv_bfloat16* A = (qq < 12) ? Aas : Ahs;
        const __nv_bfloat16* B = Wp + ((qq < 12) ? 0 : (size_t)768 * 512);
        uint32_t ab = sb + (uint32_t)buf * 28672u;
        int arow = bm + lrow; if (arow >= M) arow = M - 1;
        const __nv_bfloat16* asrc = A + (size_t)arow * 512 + a_srcoff(p) + (lseg >> 1);
        #pragma unroll
        for (int j = 0; j < 4; j++)
            cp16(ab + sw128((uint32_t)lrow * 128 + lseg + j * 16), asrc + j * 8);
        if (tid < 192) {
            uint32_t bb = ab + 16384u;
            const __nv_bfloat16* bsrc = B + (size_t)(bn + lrow) * 512 + b_srcoff(p) + (lseg >> 1);
            #pragma unroll
            for (int j = 0; j < 4; j++)
                cp16(bb + sw128((uint32_t)lrow * 128 + lseg + j * 16), bsrc + j * 8);
        }
    };

    load_panel(0, 0); cp_commit();
    load_panel(1, 1); cp_commit();

    for (int qq = 0; qq < 24; qq++) {
        if (qq == 23) cp_wait0(); else cp_wait1();
        __syncthreads();
        if (qq + 2 < 24) { load_panel((qq + 2) % 3, qq + 2); cp_commit(); }
        uint32_t ab = sb + (uint32_t)(qq % 3) * 28672u;
        uint32_t bb = ab + 16384u;
        int sw = qq / 12;
        #pragma unroll
        for (int ks = 0; ks < 4; ks++) {
            uint32_t a[2][4];
            #pragma unroll
            for (int im = 0; im < 2; im++) {
                uint32_t r  = wm + im * 16 + (lane & 15);
                uint32_t cb = ks * 32 + ((lane >> 4) << 4);
                ldm_x4(a[im], ab + sw128(r * 128 + cb));
            }
            uint32_t b[3][4];
            #pragma unroll
            for (int ib = 0; ib < 3; ib++) {
                uint32_t r  = wn + ib * 16 + ((lane >> 4) << 3) + (lane & 7);
                uint32_t cb = ks * 32 + (((lane >> 3) & 1) << 4);
                ldm_x4(b[ib], bb + sw128(r * 128 + cb));
            }
            #pragma unroll
            for (int im = 0; im < 2; im++)
                #pragma unroll
                for (int j = 0; j < 6; j++) {
                    int part = j % 3;                 // 0=r, 1=z, 2=n
                    int g = j / 3;
                    int set = (part < 2) ? part : (2 + sw);
                    mma16816(d[set][im][g], a[im],
                             b[j >> 1][(j & 1) * 2], b[j >> 1][(j & 1) * 2 + 1]);
                }
        }
        __syncthreads();
    }

    // ---- GRU epilogue ----
    #pragma unroll
    for (int im = 0; im < 2; im++) {
        #pragma unroll
        for (int g = 0; g < 2; g++) {
            int group = blockIdx.y * 4 + (wid >> 2) * 2 + g;
            int c = group * 8 + (lane & 3) * 2;     // h-column (even)
            float bR0 = b_ih[c]       + b_hh[c];
            float bR1 = b_ih[c + 1]   + b_hh[c + 1];
            float bZ0 = b_ih[256 + c] + b_hh[256 + c];
            float bZ1 = b_ih[257 + c] + b_hh[257 + c];
            float bNi0 = b_ih[512 + c],     bNi1 = b_ih[513 + c];
            float bNh0 = b_hh[512 + c],     bNh1 = b_hh[513 + c];
            #pragma unroll
            for (int hf = 0; hf < 2; hf++) {
                int r = bm + wm + im * 16 + (lane >> 2) + hf * 8;
                if (r >= M) continue;
                int q0 = hf * 2, q1 = q0 + 1;
                float hv0 = h[(size_t)r * 256 + c];
                float hv1 = h[(size_t)r * 256 + c + 1];
                float rg0 = 1.f / (1.f + __expf(-(d[0][im][g][q0] + bR0)));
                float rg1 = 1.f / (1.f + __expf(-(d[0][im][g][q1] + bR1)));
                float zg0 = 1.f / (1.f + __expf(-(d[1][im][g][q0] + bZ0)));
                float zg1 = 1.f / (1.f + __expf(-(d[1][im][g][q1] + bZ1)));
                float ng0 = tanhf(d[2][im][g][q0] + bNi0 + rg0 * (d[3][im][g][q0] + bNh0));
                float ng1 = tanhf(d[2][im][g][q1] + bNi1 + rg1 * (d[3][im][g][q1] + bNh1));
                float o0 = (1.f - zg0) * ng0 + zg0 * hv0;
                float o1 = (1.f - zg1) * ng1 + zg1 * hv1;
                *(float2*)(hn + (size_t)r * 256 + c) = make_float2(o0, o1);
                __nv_bfloat16 h0b = __float2bfloat16(o0);
                __nv_bfloat16 h1b = __float2bfloat16(o1);
                __nv_bfloat16 l0b = __float2bfloat16(o0 - __bfloat162float(h0b));
                __nv_bfloat16 l1b = __float2bfloat16(o1 - __bfloat162float(h1b));
                *(__nv_bfloat162*)(hs_out + (size_t)r * 512 + c) = __halves2bfloat162(h0b, h1b);
                *(__nv_bfloat162*)(hs_out + (size_t)r * 512 + 256 + c) = __halves2bfloat162(l0b, l1b);
            }
        }
    }
}

// -------- aggregation: as[d] = split( sum_{e in CSR[d]} w_e * m[src_e] ) --------
__global__ void aggregate_k(const float* __restrict__ m, __nv_bfloat16* __restrict__ as, int n) {
    int warp = (blockIdx.x * blockDim.x + threadIdx.x) >> 5;
    int lane = threadIdx.x & 31;
    if (warp >= n) return;
    int s = g_rowptr[warp], e = g_rowptr[warp + 1];
    float4 a0 = make_float4(0.f, 0.f, 0.f, 0.f);
    float4 a1 = make_float4(0.f, 0.f, 0.f, 0.f);
    for (int i = s; i < e; i++) {
        int src = g_col[i];
        float w = g_ewS[i];
        const float4* row = (const float4*)(m + (size_t)src * HDIM);
        float4 v0 = row[lane];
        float4 v1 = row[lane + 32];
        a0.x += w * v0.x; a0.y += w * v0.y; a0.z += w * v0.z; a0.w += w * v0.w;
        a1.x += w * v1.x; a1.y += w * v1.y; a1.z += w * v1.z; a1.w += w * v1.w;
    }
    __nv_bfloat16* row = as + (size_t)warp * 512;
    split4(a0, (__nv_bfloat162*)(row + lane * 4),       (__nv_bfloat162*)(row + 256 + lane * 4));
    split4(a1, (__nv_bfloat162*)(row + 128 + lane * 4), (__nv_bfloat162*)(row + 384 + lane * 4));
}

// ---------------- final: out[n] = relu(h[n]) . fc_w + fc_b ----------------------
__global__ void final_k(const float* __restrict__ h, const float* __restrict__ fcw,
                        const float* __restrict__ fcb, float* __restrict__ out, int n) {
    int warp = (blockIdx.x * blockDim.x + threadIdx.x) >> 5;
    int lane = threadIdx.x & 31;
    if (warp >= n) return;
    const float4* hr = (const float4*)(h + (size_t)warp * HDIM);
    const float4* wr = (const float4*)fcw;
    float s = 0.f;
    #pragma unroll
    for (int l = 0; l < 2; l++) {
        float4 v = hr[lane + 32 * l];
        float4 w = wr[lane + 32 * l];
        s += fmaxf(v.x, 0.f) * w.x + fmaxf(v.y, 0.f) * w.y +
             fmaxf(v.z, 0.f) * w.z + fmaxf(v.w, 0.f) * w.w;
    }
    #pragma unroll
    for (int o = 16; o > 0; o >>= 1) s += __shfl_xor_sync(0xFFFFFFFFu, s, o);
    if (lane == 0) out[warp] = s + fcb[0];
}

// ---------------- host orchestration -------------------------------------------
extern "C" void kernel_launch(void* const* d_in, const int* in_sizes, int n_in,
                              void* d_out, int out_size) {
    const float* x    = (const float*)d_in[0];
    const void*  ei   = d_in[1];
    const float* ew   = (const float*)d_in[2];
    const float* wL   = (const float*)d_in[3];
    const float* w_ih = (const float*)d_in[4];
    const float* w_hh = (const float*)d_in[5];
    const float* b_ih = (const float*)d_in[6];
    const float* b_hh = (const float*)d_in[7];
    const float* fcw  = (const float*)d_in[8];
    const float* fcb  = (const float*)d_in[9];

    int H = in_sizes[8];            // 256
    int N = in_sizes[0] / H;        // 50000
    int E = in_sizes[2];            // 800000
    int L = in_sizes[3] / (H * H);  // 5

    float *h0, *h1, *m, *wt;
    int* cnt;
    __nv_bfloat16 *hsA, *hsB, *as, *wts, *wgp;
    cudaGetSymbolAddress((void**)&h0,  g_h0);
    cudaGetSymbolAddress((void**)&h1,  g_h1);
    cudaGetSymbolAddress((void**)&m,   g_m);
    cudaGetSymbolAddress((void**)&wt,  g_wt);
    cudaGetSymbolAddress((void**)&cnt, g_cnt);
    cudaGetSymbolAddress((void**)&hsA, g_hsA);
    cudaGetSymbolAddress((void**)&hsB, g_hsB);
    cudaGetSymbolAddress((void**)&as,  g_as);
    cudaGetSymbolAddress((void**)&wts, g_wts);
    cudaGetSymbolAddress((void**)&wgp, g_wgp);

    cudaFuncSetAttribute(gemm_mma, cudaFuncAttributeMaxDynamicSharedMemorySize, GEMM_SMEM);
    cudaFuncSetAttribute(gemm_gru, cudaFuncAttributeMaxDynamicSharedMemorySize, FUSE_SMEM);

    cudaMemcpyAsync(h0, x, (size_t)N * H * sizeof(float), cudaMemcpyDeviceToDevice);
    cudaMemsetAsync(cnt, 0, (size_t)N * sizeof(int));

    int nb = (N + 255) / 256;
    detect_k<<<1, 256>>>((const unsigned int*)ei, E);
    {
        dim3 b(32, 32), g(H / 32, H / 32, L);
        transpose_k<<<g, b>>>(wL, wt);
    }
    count_k<<<(E + 255) / 256, 256>>>(ei, E);
    scanA_k<<<nb, 256>>>(N);
    scanB_k<<<1, 256>>>(nb);
    scanC_k<<<nb, 256>>>(N, E);
    scatter_k<<<(E + 255) / 256, 256>>>(ei, ew, E);

    // weight splits
    split_k<<<((size_t)L * H * 64 + 255) / 256, 256>>>(wt, wts, L * H);
    permsplit_k<<<(768 * 64 + 255) / 256, 256>>>(w_ih, wgp);
    permsplit_k<<<(768 * 64 + 255) / 256, 256>>>(w_hh, wgp + (size_t)768 * 512);
    split_k<<<((size_t)N * 64 + 255) / 256, 256>>>(h0, hsA, N);

    float* hc = h0;
    float* hx = h1;
    __nv_bfloat16* hscur = hsA;
    __nv_bfloat16* hsnxt = hsB;
    int mtiles = (N + 127) / 128;
    dim3 gm_(mtiles, 2);     // m-GEMM: Ntot=256
    dim3 gf_(mtiles, 8);     // fused: 8 n-tiles of 96

    for (int l = 0; l < L; l++) {
        gemm_mma<<<gm_, 256, GEMM_SMEM>>>(hscur, wts + (size_t)l * H * 512, m, N, H);
        aggregate_k<<<((size_t)N * 32 + 255) / 256, 256>>>(m, as, N);
        gemm_gru<<<gf_, 256, FUSE_SMEM>>>(as, hscur, wgp, b_ih, b_hh, hc, hx, hsnxt, N);
        float* t = hc; hc = hx; hx = t;
        __nv_bfloat16* u = hscur; hscur = hsnxt; hsnxt = u;
    }
    final_k<<<((size_t)N * 32 + 255) / 256, 256>>>(hc, fcw, fcb, (float*)d_out, N);
}

// round 15
// speedup vs baseline: 1.6953x; 1.6953x over previous
#include <cuda_runtime.h>
#include <cuda_bf16.h>
#include <math.h>
#include <stdint.h>

#define HDIM 256
#define NMAX 50176
#define EMAX 800032
#define LMAX 8

// ---------------- scratch (static device globals; no allocation) ----------------
__device__ float g_h0 [(size_t)NMAX * HDIM];
__device__ float g_h1 [(size_t)NMAX * HDIM];
__device__ float g_gi [(size_t)NMAX * 3 * HDIM];
__device__ float g_gh [(size_t)NMAX * 3 * HDIM];
__device__ float g_wcf[(size_t)3 * HDIM * HDIM];          // per-layer combined weight fp32
__device__ int   g_rowptr[NMAX + 1];
__device__ int   g_fill[NMAX];
__device__ int   g_cnt [NMAX];
__device__ int   g_bsum[256];
__device__ int   g_boff[256];
__device__ int   g_col [EMAX];
__device__ float g_ewS [EMAX];
__device__ int   g_is64;
// bf16 split buffers: layout [rows x 512] = [hi(256) | lo(256)]
__device__ __nv_bfloat16 g_hs  [(size_t)NMAX * 512];
__device__ __nv_bfloat16 g_as  [(size_t)NMAX * 512];
__device__ __nv_bfloat16 g_wls [(size_t)LMAX * HDIM * 512];      // split of W[l] (row-major)
__device__ __nv_bfloat16 g_wcs [(size_t)LMAX * 3 * HDIM * 512];  // split of combined Wc[l]
__device__ __nv_bfloat16 g_wihs[(size_t)3 * HDIM * 512];
__device__ __nv_bfloat16 g_whhs[(size_t)3 * HDIM * 512];

// ---------------- small PTX helpers (baseline ISA only) -------------------------
__device__ __forceinline__ uint32_t s2u(const void* p) {
    uint32_t a;
    asm("{ .reg .u64 t; cvta.to.shared.u64 t, %1; cvt.u32.u64 %0, t; }" : "=r"(a) : "l"(p));
    return a;
}
__device__ __forceinline__ uint32_t sw128(uint32_t off) { return off ^ ((off >> 3) & 0x70); }
__device__ __forceinline__ void cp16(uint32_t saddr, const void* g) {
    asm volatile("cp.async.cg.shared.global [%0], [%1], 16;" :: "r"(saddr), "l"(g) : "memory");
}
__device__ __forceinline__ void cp_commit() { asm volatile("cp.async.commit_group;" ::: "memory"); }
__device__ __forceinline__ void cp_wait0()  { asm volatile("cp.async.wait_group 0;" ::: "memory"); }
__device__ __forceinline__ void cp_wait1()  { asm volatile("cp.async.wait_group 1;" ::: "memory"); }
__device__ __forceinline__ void ldm_x4(uint32_t* r, uint32_t addr) {
    asm volatile("ldmatrix.sync.aligned.m8n8.x4.shared.b16 {%0,%1,%2,%3}, [%4];"
                 : "=r"(r[0]), "=r"(r[1]), "=r"(r[2]), "=r"(r[3]) : "r"(addr));
}
__device__ __forceinline__ void mma16816(float* d, const uint32_t* a, uint32_t b0, uint32_t b1) {
    asm volatile(
        "mma.sync.aligned.m16n8k16.row.col.f32.bf16.bf16.f32 "
        "{%0,%1,%2,%3}, {%4,%5,%6,%7}, {%8,%9}, {%0,%1,%2,%3};"
        : "+f"(d[0]), "+f"(d[1]), "+f"(d[2]), "+f"(d[3])
        : "r"(a[0]), "r"(a[1]), "r"(a[2]), "r"(a[3]), "r"(b0), "r"(b1));
}

// ---------------- edge-index dtype detection (int64 vs int32) -------------------
__global__ void detect_k(const unsigned int* p, int E) {
    __shared__ int any;
    if (threadIdx.x == 0) any = 0;
    __syncthreads();
    int acc = 0;
    int nchk = 2048;
    for (int i = threadIdx.x; i < nchk; i += blockDim.x)
        acc |= (int)p[2 * i + 1];
    if (acc) atomicOr(&any, 1);
    __syncthreads();
    if (threadIdx.x == 0) g_is64 = (any == 0) ? 1 : 0;
}

__device__ __forceinline__ int eidx(const void* p, long long pos) {
    if (g_is64) return (int)((const long long*)p)[pos];
    return ((const int*)p)[pos];
}

// ---------------- CSR build ------------------------------------------------------
__global__ void count_k(const void* ei, int E) {
    int i = blockIdx.x * blockDim.x + threadIdx.x;
    if (i < E) atomicAdd(&g_cnt[eidx(ei, (long long)E + i)], 1);
}

__global__ void scanA_k(int n) {
    __shared__ int sh[256];
    int t = threadIdx.x;
    int i = blockIdx.x * 256 + t;
    int v = (i < n) ? g_cnt[i] : 0;
    sh[t] = v;
    __syncthreads();
    #pragma unroll
    for (int off = 1; off < 256; off <<= 1) {
        int tv = (t >= off) ? sh[t - off] : 0;
        __syncthreads();
        sh[t] += tv;
        __syncthreads();
    }
    if (i < n) g_rowptr[i] = sh[t] - v;
    if (t == 255) g_bsum[blockIdx.x] = sh[255];
}
__global__ void scanB_k(int nb) {
    __shared__ int sh[256];
    int t = threadIdx.x;
    int v = (t < nb) ? g_bsum[t] : 0;
    sh[t] = v;
    __syncthreads();
    #pragma unroll
    for (int off = 1; off < 256; off <<= 1) {
        int tv = (t >= off) ? sh[t - off] : 0;
        __syncthreads();
        sh[t] += tv;
        __syncthreads();
    }
    g_boff[t] = sh[t] - v;
}
__global__ void scanC_k(int n, int E) {
    int i = blockIdx.x * 256 + threadIdx.x;
    if (i < n) {
        int r = g_rowptr[i] + g_boff[blockIdx.x];
        g_rowptr[i] = r;
        g_fill[i]   = r;
    }
    if (i == 0) g_rowptr[n] = E;
}

__global__ void scatter_k(const void* ei, const float* __restrict__ ew, int E) {
    int i = blockIdx.x * blockDim.x + threadIdx.x;
    if (i >= E) return;
    int d = eidx(ei, (long long)E + i);
    int s = eidx(ei, i);
    int pos = atomicAdd(&g_fill[d], 1);
    g_col[pos] = s;
    g_ewS[pos] = ew[i];
}

// ---------------- fp32 -> bf16 (hi|lo) split: [rows x 256] -> [rows x 512] ------
__device__ __forceinline__ void split4(float4 v, __nv_bfloat162* oh, __nv_bfloat162* ol) {
    __nv_bfloat16 hx = __float2bfloat16(v.x);
    __nv_bfloat16 hy = __float2bfloat16(v.y);
    __nv_bfloat16 hz = __float2bfloat16(v.z);
    __nv_bfloat16 hw = __float2bfloat16(v.w);
    oh[0] = __halves2bfloat162(hx, hy);
    oh[1] = __halves2bfloat162(hz, hw);
    ol[0] = __halves2bfloat162(__float2bfloat16(v.x - __bfloat162float(hx)),
                               __float2bfloat16(v.y - __bfloat162float(hy)));
    ol[1] = __halves2bfloat162(__float2bfloat16(v.z - __bfloat162float(hz)),
                               __float2bfloat16(v.w - __bfloat162float(hw)));
}

__global__ void split_k(const float* __restrict__ in, __nv_bfloat16* __restrict__ out, int rows) {
    int idx = blockIdx.x * blockDim.x + threadIdx.x;
    int total = rows * 64;
    if (idx >= total) return;
    int r = idx >> 6, c4 = idx & 63;
    float4 v = ((const float4*)(in + (size_t)r * HDIM))[c4];
    split4(v, (__nv_bfloat162*)(out + (size_t)r * 512 + c4 * 4),
              (__nv_bfloat162*)(out + (size_t)r * 512 + 256 + c4 * 4));
}

// ---------------- panel source offsets (12 K-panels of 64) -----------------------
__device__ __forceinline__ int a_srcoff(int p) {
    return (p < 4) ? p * 64 : (p < 8) ? 256 + (p - 4) * 64 : (p - 8) * 64;
}
__device__ __forceinline__ int b_srcoff(int p) {
    return (p < 8) ? (p & 3) * 64 : 256 + (p - 8) * 64;
}

// ---------------- warp-mma (HMMA) bf16 split-K GEMM, 3-stage pipeline ------------
// C[M, Ntot] = Afp32 * Bfp32^T + bias, via bf16 (hi,lo) split operands.
// blockIdx.z selects (A, B, bias, C) pair.
#define GEMM_SMEM 98304

__global__ void __launch_bounds__(256, 2)
gemm_mma(const __nv_bfloat16* __restrict__ A0, const __nv_bfloat16* __restrict__ A1,
         const __nv_bfloat16* __restrict__ B0, const __nv_bfloat16* __restrict__ B1,
         const float* __restrict__ bias0, const float* __restrict__ bias1,
         float* __restrict__ C0, float* __restrict__ C1, int M, int Ntot) {
    extern __shared__ char smem[];
    uint32_t sb = s2u(smem);
    int tid = threadIdx.x, wid = tid >> 5, lane = tid & 31;
    int bm = blockIdx.x * 128, bn = blockIdx.y * 128;
    const __nv_bfloat16* A = blockIdx.z ? A1 : A0;
    const __nv_bfloat16* B = blockIdx.z ? B1 : B0;
    const float* bias = blockIdx.z ? bias1 : bias0;
    float* C = blockIdx.z ? C1 : C0;
    int wm = (wid & 3) * 32;
    int wn = (wid >> 2) * 64;

    float d[2][8][4];
    #pragma unroll
    for (int i = 0; i < 2; i++)
        #pragma unroll
        for (int j = 0; j < 8; j++)
            #pragma unroll
            for (int q = 0; q < 4; q++) d[i][j][q] = 0.f;

    int lrow = tid >> 1;
    int lseg = (tid & 1) * 64;
    auto load_panel = [&](int buf, int p) {
        uint32_t ab = sb + (uint32_t)buf * 32768u;
        uint32_t bb = ab + 16384u;
        int arow = bm + lrow; if (arow >= M) arow = M - 1;
        const __nv_bfloat16* asrc = A + (size_t)arow * 512 + a_srcoff(p) + (lseg >> 1);
        const __nv_bfloat16* bsrc = B + (size_t)(bn + lrow) * 512 + b_srcoff(p) + (lseg >> 1);
        #pragma unroll
        for (int j = 0; j < 4; j++) {
            cp16(ab + sw128((uint32_t)lrow * 128 + lseg + j * 16), asrc + j * 8);
            cp16(bb + sw128((uint32_t)lrow * 128 + lseg + j * 16), bsrc + j * 8);
        }
    };

    load_panel(0, 0); cp_commit();
    load_panel(1, 1); cp_commit();

    for (int p = 0; p < 12; p++) {
        if (p == 11) cp_wait0(); else cp_wait1();
        __syncthreads();
        if (p + 2 < 12) { load_panel((p + 2) % 3, p + 2); cp_commit(); }
        uint32_t ab = sb + (uint32_t)(p % 3) * 32768u;
        uint32_t bb = ab + 16384u;
        #pragma unroll
        for (int ks = 0; ks < 4; ks++) {
            uint32_t a[2][4];
            #pragma unroll
            for (int im = 0; im < 2; im++) {
                uint32_t r  = wm + im * 16 + (lane & 15);
                uint32_t cb = ks * 32 + ((lane >> 4) << 4);
                ldm_x4(a[im], ab + sw128(r * 128 + cb));
            }
            uint32_t b[4][4];
            #pragma unroll
            for (int ib = 0; ib < 4; ib++) {
                uint32_t r  = wn + ib * 16 + ((lane >> 4) << 3) + (lane & 7);
                uint32_t cb = ks * 32 + (((lane >> 3) & 1) << 4);
                ldm_x4(b[ib], bb + sw128(r * 128 + cb));
            }
            #pragma unroll
            for (int im = 0; im < 2; im++)
                #pragma unroll
                for (int in8 = 0; in8 < 8; in8++)
                    mma16816(d[im][in8], a[im], b[in8 >> 1][(in8 & 1) * 2],
                             b[in8 >> 1][(in8 & 1) * 2 + 1]);
        }
        __syncthreads();
    }

    #pragma unroll
    for (int in8 = 0; in8 < 8; in8++) {
        int col = bn + wn + in8 * 8 + (lane & 3) * 2;
        float b0 = 0.f, b1 = 0.f;
        if (bias) { b0 = bias[col]; b1 = bias[col + 1]; }
        #pragma unroll
        for (int im = 0; im < 2; im++) {
            int r0 = bm + wm + im * 16 + (lane >> 2);
            if (r0 < M)
                *(float2*)(C + (size_t)r0 * Ntot + col) =
                    make_float2(d[im][in8][0] + b0, d[im][in8][1] + b1);
            int r1 = r0 + 8;
            if (r1 < M)
                *(float2*)(C + (size_t)r1 * Ntot + col) =
                    make_float2(d[im][in8][2] + b0, d[im][in8][3] + b1);
        }
    }
}

// -------- aggregation: as[d] = split( sum_{e in CSR[d]} w_e * h[src_e] ) --------
// (aggregation commutes with the linear transform; combined weight handles @W)
__global__ void aggregate_k(const float* __restrict__ h, __nv_bfloat16* __restrict__ as, int n) {
    int warp = (blockIdx.x * blockDim.x + threadIdx.x) >> 5;
    int lane = threadIdx.x & 31;
    if (warp >= n) return;
    int s = g_rowptr[warp], e = g_rowptr[warp + 1];
    float4 a0 = make_float4(0.f, 0.f, 0.f, 0.f);
    float4 a1 = make_float4(0.f, 0.f, 0.f, 0.f);
    for (int i = s; i < e; i++) {
        int src = g_col[i];
        float w = g_ewS[i];
        const float4* row = (const float4*)(h + (size_t)src * HDIM);
        float4 v0 = row[lane];
        float4 v1 = row[lane + 32];
        a0.x += w * v0.x; a0.y += w * v0.y; a0.z += w * v0.z; a0.w += w * v0.w;
        a1.x += w * v1.x; a1.y += w * v1.y; a1.z += w * v1.z; a1.w += w * v1.w;
    }
    __nv_bfloat16* row = as + (size_t)warp * 512;
    split4(a0, (__nv_bfloat162*)(row + lane * 4),       (__nv_bfloat162*)(row + 256 + lane * 4));
    split4(a1, (__nv_bfloat162*)(row + 128 + lane * 4), (__nv_bfloat162*)(row + 384 + lane * 4));
}

// ---------------- GRU gates (fused split output for next layer) -----------------
__device__ __forceinline__ float sigf(float x) { return 1.f / (1.f + __expf(-x)); }
__device__ __forceinline__ float gru1(float gir, float giz, float gin,
                                      float ghr, float ghz, float ghn, float h) {
    float r = sigf(gir + ghr);
    float z = sigf(giz + ghz);
    float n = tanhf(gin + r * ghn);
    return (1.f - z) * n + z * h;
}

__global__ void gru_k(const float* __restrict__ gi, const float* __restrict__ gh,
                      const float* __restrict__ h, float* __restrict__ hn,
                      __nv_bfloat16* __restrict__ hs, int n) {
    int idx = blockIdx.x * blockDim.x + threadIdx.x;
    int total = n * (HDIM / 4);
    if (idx >= total) return;
    int row = idx / (HDIM / 4), c4 = idx % (HDIM / 4);
    const float4* gir = (const float4*)(gi + (size_t)row * 3 * HDIM) + c4;
    const float4* ghr = (const float4*)(gh + (size_t)row * 3 * HDIM) + c4;
    float4 ir = gir[0], iz = gir[HDIM / 4], in_ = gir[2 * (HDIM / 4)];
    float4 hr = ghr[0], hz = ghr[HDIM / 4], hn_ = ghr[2 * (HDIM / 4)];
    float4 hv = ((const float4*)(h + (size_t)row * HDIM))[c4];
    float4 o;
    o.x = gru1(ir.x, iz.x, in_.x, hr.x, hz.x, hn_.x, hv.x);
    o.y = gru1(ir.y, iz.y, in_.y, hr.y, hz.y, hn_.y, hv.y);
    o.z = gru1(ir.z, iz.z, in_.z, hr.z, hz.z, hn_.z, hv.z);
    o.w = gru1(ir.w, iz.w, in_.w, hr.w, hz.w, hn_.w, hv.w);
    ((float4*)(hn + (size_t)row * HDIM))[c4] = o;
    __nv_bfloat16* srow = hs + (size_t)row * 512;
    split4(o, (__nv_bfloat162*)(srow + c4 * 4), (__nv_bfloat162*)(srow + 256 + c4 * 4));
}

// ---------------- final: out[n] = relu(h[n]) . fc_w + fc_b ----------------------
__global__ void final_k(const float* __restrict__ h, const float* __restrict__ fcw,
                        const float* __restrict__ fcb, float* __restrict__ out, int n) {
    int warp = (blockIdx.x * blockDim.x + threadIdx.x) >> 5;
    int lane = threadIdx.x & 31;
    if (warp >= n) return;
    const float4* hr = (const float4*)(h + (size_t)warp * HDIM);
    const float4* wr = (const float4*)fcw;
    float s = 0.f;
    #pragma unroll
    for (int l = 0; l < 2; l++) {
        float4 v = hr[lane + 32 * l];
        float4 w = wr[lane + 32 * l];
        s += fmaxf(v.x, 0.f) * w.x + fmaxf(v.y, 0.f) * w.y +
             fmaxf(v.z, 0.f) * w.z + fmaxf(v.w, 0.f) * w.w;
    }
    #pragma unroll
    for (int o = 16; o > 0; o >>= 1) s += __shfl_xor_sync(0xFFFFFFFFu, s, o);
    if (lane == 0) out[warp] = s + fcb[0];
}

// ---------------- host orchestration -------------------------------------------
extern "C" void kernel_launch(void* const* d_in, const int* in_sizes, int n_in,
                              void* d_out, int out_size) {
    const float* x    = (const float*)d_in[0];
    const void*  ei   = d_in[1];
    const float* ew   = (const float*)d_in[2];
    const float* wL   = (const float*)d_in[3];
    const float* w_ih = (const float*)d_in[4];
    const float* w_hh = (const float*)d_in[5];
    const float* b_ih = (const float*)d_in[6];
    const float* b_hh = (const float*)d_in[7];
    const float* fcw  = (const float*)d_in[8];
    const float* fcb  = (const float*)d_in[9];

    int H = in_sizes[8];            // 256
    int N = in_sizes[0] / H;        // 50000
    int E = in_sizes[2];            // 800000
    int L = in_sizes[3] / (H * H);  // 5

    float *h0, *h1, *gi, *gh, *wcf;
    int* cnt;
    __nv_bfloat16 *hs, *as, *wls, *wcs, *wihs, *whhs;
    cudaGetSymbolAddress((void**)&h0,   g_h0);
    cudaGetSymbolAddress((void**)&h1,   g_h1);
    cudaGetSymbolAddress((void**)&gi,   g_gi);
    cudaGetSymbolAddress((void**)&gh,   g_gh);
    cudaGetSymbolAddress((void**)&wcf,  g_wcf);
    cudaGetSymbolAddress((void**)&cnt,  g_cnt);
    cudaGetSymbolAddress((void**)&hs,   g_hs);
    cudaGetSymbolAddress((void**)&as,   g_as);
    cudaGetSymbolAddress((void**)&wls,  g_wls);
    cudaGetSymbolAddress((void**)&wcs,  g_wcs);
    cudaGetSymbolAddress((void**)&wihs, g_wihs);
    cudaGetSymbolAddress((void**)&whhs, g_whhs);

    cudaFuncSetAttribute(gemm_mma, cudaFuncAttributeMaxDynamicSharedMemorySize, GEMM_SMEM);

    cudaMemcpyAsync(h0, x, (size_t)N * H * sizeof(float), cudaMemcpyDeviceToDevice);
    cudaMemsetAsync(cnt, 0, (size_t)N * sizeof(int));

    int nb = (N + 255) / 256;
    detect_k<<<1, 256>>>((const unsigned int*)ei, E);
    count_k<<<(E + 255) / 256, 256>>>(ei, E);
    scanA_k<<<nb, 256>>>(N);
    scanB_k<<<1, 256>>>(nb);
    scanC_k<<<nb, 256>>>(N, E);
    scatter_k<<<(E + 255) / 256, 256>>>(ei, ew, E);

    // weight splits (fp32 -> bf16 hi|lo)
    split_k<<<((size_t)L * H * 64 + 255) / 256, 256>>>(wL, wls, L * H);     // W row-major
    split_k<<<((size_t)3 * H * 64 + 255) / 256, 256>>>(w_ih, wihs, 3 * H);
    split_k<<<((size_t)3 * H * 64 + 255) / 256, 256>>>(w_hh, whhs, 3 * H);
    split_k<<<((size_t)N * 64 + 255) / 256, 256>>>(h0, hs, N);

    // combined weights: Wc[l][c,k] = sum_j w_ih[c,j] * W[l][k,j]  (so gi = agg_h @ Wc^T)
    {
        dim3 gw((768 + 127) / 128, 2, 1);   // M=768, Ntot=256
        for (int l = 0; l < L; l++) {
            gemm_mma<<<gw, 256, GEMM_SMEM>>>(wihs, wihs,
                                             wls + (size_t)l * H * 512, wls + (size_t)l * H * 512,
                                             nullptr, nullptr, wcf, wcf, 3 * H, H);
            split_k<<<(768 * 64 + 255) / 256, 256>>>(wcf, wcs + (size_t)l * 768 * 512, 3 * H);
        }
    }

    float* hc = h0;
    float* hx = h1;
    int mtiles = (N + 127) / 128;
    dim3 gg_(mtiles, 6, 2);     // Ntot = 768, z: 0 = gi (combined W), 1 = gh

    for (int l = 0; l < L; l++) {
        aggregate_k<<<((size_t)N * 32 + 255) / 256, 256>>>(hc, as, N);
        gemm_mma<<<gg_, 256, GEMM_SMEM>>>(as, hs,
                                          wcs + (size_t)l * 768 * 512, whhs,
                                          b_ih, b_hh, gi, gh, N, 3 * H);
        gru_k<<<((size_t)N * (H / 4) + 255) / 256, 256>>>(gi, gh, hc, hx, hs, N);
        float* t = hc; hc = hx; hx = t;
    }
    final_k<<<((size_t)N * 32 + 255) / 256, 256>>>(hc, fcw, fcb, (float*)d_out, N);
}

// round 16
// speedup vs baseline: 1.7225x; 1.0161x over previous
#include <cuda_runtime.h>
#include <cuda_bf16.h>
#include <math.h>
#include <stdint.h>

#define HDIM 256
#define NMAX 50176
#define EMAX 800032
#define LMAX 8

// ---------------- scratch (static device globals; no allocation) ----------------
__device__ float g_h0 [(size_t)NMAX * HDIM];
__device__ float g_h1 [(size_t)NMAX * HDIM];
__device__ float g_gi [(size_t)NMAX * 3 * HDIM];
__device__ float g_gh [(size_t)NMAX * 3 * HDIM];
__device__ float g_wcf[(size_t)3 * HDIM * HDIM];          // per-layer combined weight fp32
__device__ int   g_rowptr[NMAX + 1];
__device__ int   g_fill[NMAX];
__device__ int   g_cnt [NMAX];
__device__ int   g_bsum[256];
__device__ int   g_boff[256];
__device__ int   g_col [EMAX];
__device__ float g_ewS [EMAX];
__device__ int   g_is64;
// bf16 split buffers: layout [rows x 512] = [hi(256) | lo(256)]
__device__ __nv_bfloat16 g_hs  [(size_t)NMAX * 512];
__device__ __nv_bfloat16 g_as  [(size_t)NMAX * 512];
__device__ __nv_bfloat16 g_wls [(size_t)LMAX * HDIM * 512];      // split of W[l] (row-major)
__device__ __nv_bfloat16 g_wcs [(size_t)LMAX * 3 * HDIM * 512];  // split of combined Wc[l]
__device__ __nv_bfloat16 g_wihs[(size_t)3 * HDIM * 512];
__device__ __nv_bfloat16 g_whhs[(size_t)3 * HDIM * 512];

// ---------------- small PTX helpers (baseline ISA only) -------------------------
__device__ __forceinline__ uint32_t s2u(const void* p) {
    uint32_t a;
    asm("{ .reg .u64 t; cvta.to.shared.u64 t, %1; cvt.u32.u64 %0, t; }" : "=r"(a) : "l"(p));
    return a;
}
__device__ __forceinline__ uint32_t sw128(uint32_t off) { return off ^ ((off >> 3) & 0x70); }
__device__ __forceinline__ void cp16(uint32_t saddr, const void* g) {
    asm volatile("cp.async.cg.shared.global [%0], [%1], 16;" :: "r"(saddr), "l"(g) : "memory");
}
__device__ __forceinline__ void cp_commit() { asm volatile("cp.async.commit_group;" ::: "memory"); }
__device__ __forceinline__ void cp_wait0()  { asm volatile("cp.async.wait_group 0;" ::: "memory"); }
__device__ __forceinline__ void cp_wait1()  { asm volatile("cp.async.wait_group 1;" ::: "memory"); }
__device__ __forceinline__ void ldm_x4(uint32_t* r, uint32_t addr) {
    asm volatile("ldmatrix.sync.aligned.m8n8.x4.shared.b16 {%0,%1,%2,%3}, [%4];"
                 : "=r"(r[0]), "=r"(r[1]), "=r"(r[2]), "=r"(r[3]) : "r"(addr));
}
__device__ __forceinline__ void mma16816(float* d, const uint32_t* a, uint32_t b0, uint32_t b1) {
    asm volatile(
        "mma.sync.aligned.m16n8k16.row.col.f32.bf16.bf16.f32 "
        "{%0,%1,%2,%3}, {%4,%5,%6,%7}, {%8,%9}, {%0,%1,%2,%3};"
        : "+f"(d[0]), "+f"(d[1]), "+f"(d[2]), "+f"(d[3])
        : "r"(a[0]), "r"(a[1]), "r"(a[2]), "r"(a[3]), "r"(b0), "r"(b1));
}

// ---------------- edge-index dtype detection (int64 vs int32) -------------------
__global__ void detect_k(const unsigned int* p, int E) {
    __shared__ int any;
    if (threadIdx.x == 0) any = 0;
    __syncthreads();
    int acc = 0;
    int nchk = 2048;
    for (int i = threadIdx.x; i < nchk; i += blockDim.x)
        acc |= (int)p[2 * i + 1];
    if (acc) atomicOr(&any, 1);
    __syncthreads();
    if (threadIdx.x == 0) g_is64 = (any == 0) ? 1 : 0;
}

__device__ __forceinline__ int eidx(const void* p, long long pos) {
    if (g_is64) return (int)((const long long*)p)[pos];
    return ((const int*)p)[pos];
}

// ---------------- CSR build ------------------------------------------------------
__global__ void count_k(const void* ei, int E) {
    int i = blockIdx.x * blockDim.x + threadIdx.x;
    if (i < E) atomicAdd(&g_cnt[eidx(ei, (long long)E + i)], 1);
}

__global__ void scanA_k(int n) {
    __shared__ int sh[256];
    int t = threadIdx.x;
    int i = blockIdx.x * 256 + t;
    int v = (i < n) ? g_cnt[i] : 0;
    sh[t] = v;
    __syncthreads();
    #pragma unroll
    for (int off = 1; off < 256; off <<= 1) {
        int tv = (t >= off) ? sh[t - off] : 0;
        __syncthreads();
        sh[t] += tv;
        __syncthreads();
    }
    if (i < n) g_rowptr[i] = sh[t] - v;
    if (t == 255) g_bsum[blockIdx.x] = sh[255];
}
__global__ void scanB_k(int nb) {
    __shared__ int sh[256];
    int t = threadIdx.x;
    int v = (t < nb) ? g_bsum[t] : 0;
    sh[t] = v;
    __syncthreads();
    #pragma unroll
    for (int off = 1; off < 256; off <<= 1) {
        int tv = (t >= off) ? sh[t - off] : 0;
        __syncthreads();
        sh[t] += tv;
        __syncthreads();
    }
    g_boff[t] = sh[t] - v;
}
__global__ void scanC_k(int n, int E) {
    int i = blockIdx.x * 256 + threadIdx.x;
    if (i < n) {
        int r = g_rowptr[i] + g_boff[blockIdx.x];
        g_rowptr[i] = r;
        g_fill[i]   = r;
    }
    if (i == 0) g_rowptr[n] = E;
}

__global__ void scatter_k(const void* ei, const float* __restrict__ ew, int E) {
    int i = blockIdx.x * blockDim.x + threadIdx.x;
    if (i >= E) return;
    int d = eidx(ei, (long long)E + i);
    int s = eidx(ei, i);
    int pos = atomicAdd(&g_fill[d], 1);
    g_col[pos] = s;
    g_ewS[pos] = ew[i];
}

// ---------------- fp32 -> bf16 (hi|lo) split: [rows x 256] -> [rows x 512] ------
__device__ __forceinline__ void split4(float4 v, __nv_bfloat162* oh, __nv_bfloat162* ol) {
    __nv_bfloat16 hx = __float2bfloat16(v.x);
    __nv_bfloat16 hy = __float2bfloat16(v.y);
    __nv_bfloat16 hz = __float2bfloat16(v.z);
    __nv_bfloat16 hw = __float2bfloat16(v.w);
    oh[0] = __halves2bfloat162(hx, hy);
    oh[1] = __halves2bfloat162(hz, hw);
    ol[0] = __halves2bfloat162(__float2bfloat16(v.x - __bfloat162float(hx)),
                               __float2bfloat16(v.y - __bfloat162float(hy)));
    ol[1] = __halves2bfloat162(__float2bfloat16(v.z - __bfloat162float(hz)),
                               __float2bfloat16(v.w - __bfloat162float(hw)));
}

__global__ void split_k(const float* __restrict__ in, __nv_bfloat16* __restrict__ out, int rows) {
    int idx = blockIdx.x * blockDim.x + threadIdx.x;
    int total = rows * 64;
    if (idx >= total) return;
    int r = idx >> 6, c4 = idx & 63;
    float4 v = ((const float4*)(in + (size_t)r * HDIM))[c4];
    split4(v, (__nv_bfloat162*)(out + (size_t)r * 512 + c4 * 4),
              (__nv_bfloat162*)(out + (size_t)r * 512 + 256 + c4 * 4));
}

// ---------------- panel source offsets (12 K-panels of 64) -----------------------
__device__ __forceinline__ int a_srcoff(int p) {
    return (p < 4) ? p * 64 : (p < 8) ? 256 + (p - 4) * 64 : (p - 8) * 64;
}
__device__ __forceinline__ int b_srcoff(int p) {
    return (p < 8) ? (p & 3) * 64 : 256 + (p - 8) * 64;
}

// ---------------- warp-mma (HMMA) bf16 split-K GEMM, 3-stage pipeline ------------
// C[M, Ntot] = Afp32 * Bfp32^T + bias, via bf16 (hi,lo) split operands.
// blockIdx.z selects (A, B, bias, C) pair.
// Single barrier per panel: at iteration q the load targets buffer (q+2)%3,
// last read at iteration q-1; every warp passed this iteration's top barrier
// only after finishing that compute, so the top barrier alone orders both
// cp.async visibility and buffer reuse.
#define GEMM_SMEM 98304

__global__ void __launch_bounds__(256, 2)
gemm_mma(const __nv_bfloat16* __restrict__ A0, const __nv_bfloat16* __restrict__ A1,
         const __nv_bfloat16* __restrict__ B0, const __nv_bfloat16* __restrict__ B1,
         const float* __restrict__ bias0, const float* __restrict__ bias1,
         float* __restrict__ C0, float* __restrict__ C1, int M, int Ntot) {
    extern __shared__ char smem[];
    uint32_t sb = s2u(smem);
    int tid = threadIdx.x, wid = tid >> 5, lane = tid & 31;
    int bm = blockIdx.x * 128, bn = blockIdx.y * 128;
    const __nv_bfloat16* A = blockIdx.z ? A1 : A0;
    const __nv_bfloat16* B = blockIdx.z ? B1 : B0;
    const float* bias = blockIdx.z ? bias1 : bias0;
    float* C = blockIdx.z ? C1 : C0;
    int wm = (wid & 3) * 32;
    int wn = (wid >> 2) * 64;

    float d[2][8][4];
    #pragma unroll
    for (int i = 0; i < 2; i++)
        #pragma unroll
        for (int j = 0; j < 8; j++)
            #pragma unroll
            for (int q = 0; q < 4; q++) d[i][j][q] = 0.f;

    int lrow = tid >> 1;
    int lseg = (tid & 1) * 64;
    auto load_panel = [&](int buf, int p) {
        uint32_t ab = sb + (uint32_t)buf * 32768u;
        uint32_t bb = ab + 16384u;
        int arow = bm + lrow; if (arow >= M) arow = M - 1;
        const __nv_bfloat16* asrc = A + (size_t)arow * 512 + a_srcoff(p) + (lseg >> 1);
        const __nv_bfloat16* bsrc = B + (size_t)(bn + lrow) * 512 + b_srcoff(p) + (lseg >> 1);
        #pragma unroll
        for (int j = 0; j < 4; j++) {
            cp16(ab + sw128((uint32_t)lrow * 128 + lseg + j * 16), asrc + j * 8);
            cp16(bb + sw128((uint32_t)lrow * 128 + lseg + j * 16), bsrc + j * 8);
        }
    };

    load_panel(0, 0); cp_commit();
    load_panel(1, 1); cp_commit();

    for (int p = 0; p < 12; p++) {
        if (p == 11) cp_wait0(); else cp_wait1();
        __syncthreads();
        if (p + 2 < 12) { load_panel((p + 2) % 3, p + 2); cp_commit(); }
        uint32_t ab = sb + (uint32_t)(p % 3) * 32768u;
        uint32_t bb = ab + 16384u;
        #pragma unroll
        for (int ks = 0; ks < 4; ks++) {
            uint32_t a[2][4];
            #pragma unroll
            for (int im = 0; im < 2; im++) {
                uint32_t r  = wm + im * 16 + (lane & 15);
                uint32_t cb = ks * 32 + ((lane >> 4) << 4);
                ldm_x4(a[im], ab + sw128(r * 128 + cb));
            }
            uint32_t b[4][4];
            #pragma unroll
            for (int ib = 0; ib < 4; ib++) {
                uint32_t r  = wn + ib * 16 + ((lane >> 4) << 3) + (lane & 7);
                uint32_t cb = ks * 32 + (((lane >> 3) & 1) << 4);
                ldm_x4(b[ib], bb + sw128(r * 128 + cb));
            }
            #pragma unroll
            for (int im = 0; im < 2; im++)
                #pragma unroll
                for (int in8 = 0; in8 < 8; in8++)
                    mma16816(d[im][in8], a[im], b[in8 >> 1][(in8 & 1) * 2],
                             b[in8 >> 1][(in8 & 1) * 2 + 1]);
        }
        // no bottom barrier: next iteration's top barrier provides the ordering
    }

    #pragma unroll
    for (int in8 = 0; in8 < 8; in8++) {
        int col = bn + wn + in8 * 8 + (lane & 3) * 2;
        float b0 = 0.f, b1 = 0.f;
        if (bias) { b0 = bias[col]; b1 = bias[col + 1]; }
        #pragma unroll
        for (int im = 0; im < 2; im++) {
            int r0 = bm + wm + im * 16 + (lane >> 2);
            if (r0 < M)
                *(float2*)(C + (size_t)r0 * Ntot + col) =
                    make_float2(d[im][in8][0] + b0, d[im][in8][1] + b1);
            int r1 = r0 + 8;
            if (r1 < M)
                *(float2*)(C + (size_t)r1 * Ntot + col) =
                    make_float2(d[im][in8][2] + b0, d[im][in8][3] + b1);
        }
    }
}

// -------- aggregation: as[d] = split( sum_{e in CSR[d]} w_e * h[src_e] ) --------
// 2-way unrolled with dual accumulators for memory-level parallelism.
__global__ void aggregate_k(const float* __restrict__ h, __nv_bfloat16* __restrict__ as, int n) {
    int warp = (blockIdx.x * blockDim.x + threadIdx.x) >> 5;
    int lane = threadIdx.x & 31;
    if (warp >= n) return;
    int s = g_rowptr[warp], e = g_rowptr[warp + 1];
    float4 a0 = make_float4(0.f, 0.f, 0.f, 0.f);
    float4 a1 = make_float4(0.f, 0.f, 0.f, 0.f);
    float4 c0 = make_float4(0.f, 0.f, 0.f, 0.f);
    float4 c1 = make_float4(0.f, 0.f, 0.f, 0.f);
    int i = s;
    for (; i + 1 < e; i += 2) {
        int  s0 = g_col[i],     s1 = g_col[i + 1];
        float w0 = g_ewS[i],    w1 = g_ewS[i + 1];
        const float4* r0 = (const float4*)(h + (size_t)s0 * HDIM);
        const float4* r1 = (const float4*)(h + (size_t)s1 * HDIM);
        float4 u0 = r0[lane], u1 = r0[lane + 32];
        float4 v0 = r1[lane], v1 = r1[lane + 32];
        a0.x += w0 * u0.x; a0.y += w0 * u0.y; a0.z += w0 * u0.z; a0.w += w0 * u0.w;
        a1.x += w0 * u1.x; a1.y += w0 * u1.y; a1.z += w0 * u1.z; a1.w += w0 * u1.w;
        c0.x += w1 * v0.x; c0.y += w1 * v0.y; c0.z += w1 * v0.z; c0.w += w1 * v0.w;
        c1.x += w1 * v1.x; c1.y += w1 * v1.y; c1.z += w1 * v1.z; c1.w += w1 * v1.w;
    }
    if (i < e) {
        int  s0 = g_col[i];
        float w0 = g_ewS[i];
        const float4* r0 = (const float4*)(h + (size_t)s0 * HDIM);
        float4 u0 = r0[lane], u1 = r0[lane + 32];
        a0.x += w0 * u0.x; a0.y += w0 * u0.y; a0.z += w0 * u0.z; a0.w += w0 * u0.w;
        a1.x += w0 * u1.x; a1.y += w0 * u1.y; a1.z += w0 * u1.z; a1.w += w0 * u1.w;
    }
    a0.x += c0.x; a0.y += c0.y; a0.z += c0.z; a0.w += c0.w;
    a1.x += c1.x; a1.y += c1.y; a1.z += c1.z; a1.w += c1.w;
    __nv_bfloat16* row = as + (size_t)warp * 512;
    split4(a0, (__nv_bfloat162*)(row + lane * 4),       (__nv_bfloat162*)(row + 256 + lane * 4));
    split4(a1, (__nv_bfloat162*)(row + 128 + lane * 4), (__nv_bfloat162*)(row + 384 + lane * 4));
}

// ---------------- GRU gates (fused split output for next layer) -----------------
__device__ __forceinline__ float sigf(float x) { return 1.f / (1.f + __expf(-x)); }
__device__ __forceinline__ float gru1(float gir, float giz, float gin,
                                      float ghr, float ghz, float ghn, float h) {
    float r = sigf(gir + ghr);
    float z = sigf(giz + ghz);
    float n = tanhf(gin + r * ghn);
    return (1.f - z) * n + z * h;
}

__global__ void gru_k(const float* __restrict__ gi, const float* __restrict__ gh,
                      const float* __restrict__ h, float* __restrict__ hn,
                      __nv_bfloat16* __restrict__ hs, int n) {
    int idx = blockIdx.x * blockDim.x + threadIdx.x;
    int total = n * (HDIM / 4);
    if (idx >= total) return;
    int row = idx / (HDIM / 4), c4 = idx % (HDIM / 4);
    const float4* gir = (const float4*)(gi + (size_t)row * 3 * HDIM) + c4;
    const float4* ghr = (const float4*)(gh + (size_t)row * 3 * HDIM) + c4;
    float4 ir = gir[0], iz = gir[HDIM / 4], in_ = gir[2 * (HDIM / 4)];
    float4 hr = ghr[0], hz = ghr[HDIM / 4], hn_ = ghr[2 * (HDIM / 4)];
    float4 hv = ((const float4*)(h + (size_t)row * HDIM))[c4];
    float4 o;
    o.x = gru1(ir.x, iz.x, in_.x, hr.x, hz.x, hn_.x, hv.x);
    o.y = gru1(ir.y, iz.y, in_.y, hr.y, hz.y, hn_.y, hv.y);
    o.z = gru1(ir.z, iz.z, in_.z, hr.z, hz.z, hn_.z, hv.z);
    o.w = gru1(ir.w, iz.w, in_.w, hr.w, hz.w, hn_.w, hv.w);
    ((float4*)(hn + (size_t)row * HDIM))[c4] = o;
    __nv_bfloat16* srow = hs + (size_t)row * 512;
    split4(o, (__nv_bfloat162*)(srow + c4 * 4), (__nv_bfloat162*)(srow + 256 + c4 * 4));
}

// ---------------- final: out[n] = relu(h[n]) . fc_w + fc_b ----------------------
__global__ void final_k(const float* __restrict__ h, const float* __restrict__ fcw,
                        const float* __restrict__ fcb, float* __restrict__ out, int n) {
    int warp = (blockIdx.x * blockDim.x + threadIdx.x) >> 5;
    int lane = threadIdx.x & 31;
    if (warp >= n) return;
    const float4* hr = (const float4*)(h + (size_t)warp * HDIM);
    const float4* wr = (const float4*)fcw;
    float s = 0.f;
    #pragma unroll
    for (int l = 0; l < 2; l++) {
        float4 v = hr[lane + 32 * l];
        float4 w = wr[lane + 32 * l];
        s += fmaxf(v.x, 0.f) * w.x + fmaxf(v.y, 0.f) * w.y +
             fmaxf(v.z, 0.f) * w.z + fmaxf(v.w, 0.f) * w.w;
    }
    #pragma unroll
    for (int o = 16; o > 0; o >>= 1) s += __shfl_xor_sync(0xFFFFFFFFu, s, o);
    if (lane == 0) out[warp] = s + fcb[0];
}

// ---------------- host orchestration -------------------------------------------
extern "C" void kernel_launch(void* const* d_in, const int* in_sizes, int n_in,
                              void* d_out, int out_size) {
    const float* x    = (const float*)d_in[0];
    const void*  ei   = d_in[1];
    const float* ew   = (const float*)d_in[2];
    const float* wL   = (const float*)d_in[3];
    const float* w_ih = (const float*)d_in[4];
    const float* w_hh = (const float*)d_in[5];
    const float* b_ih = (const float*)d_in[6];
    const float* b_hh = (const float*)d_in[7];
    const float* fcw  = (const float*)d_in[8];
    const float* fcb  = (const float*)d_in[9];

    int H = in_sizes[8];            // 256
    int N = in_sizes[0] / H;        // 50000
    int E = in_sizes[2];            // 800000
    int L = in_sizes[3] / (H * H);  // 5

    float *h0, *h1, *gi, *gh, *wcf;
    int* cnt;
    __nv_bfloat16 *hs, *as, *wls, *wcs, *wihs, *whhs;
    cudaGetSymbolAddress((void**)&h0,   g_h0);
    cudaGetSymbolAddress((void**)&h1,   g_h1);
    cudaGetSymbolAddress((void**)&gi,   g_gi);
    cudaGetSymbolAddress((void**)&gh,   g_gh);
    cudaGetSymbolAddress((void**)&wcf,  g_wcf);
    cudaGetSymbolAddress((void**)&cnt,  g_cnt);
    cudaGetSymbolAddress((void**)&hs,   g_hs);
    cudaGetSymbolAddress((void**)&as,   g_as);
    cudaGetSymbolAddress((void**)&wls,  g_wls);
    cudaGetSymbolAddress((void**)&wcs,  g_wcs);
    cudaGetSymbolAddress((void**)&wihs, g_wihs);
    cudaGetSymbolAddress((void**)&whhs, g_whhs);

    cudaFuncSetAttribute(gemm_mma, cudaFuncAttributeMaxDynamicSharedMemorySize, GEMM_SMEM);

    cudaMemcpyAsync(h0, x, (size_t)N * H * sizeof(float), cudaMemcpyDeviceToDevice);
    cudaMemsetAsync(cnt, 0, (size_t)N * sizeof(int));

    int nb = (N + 255) / 256;
    detect_k<<<1, 256>>>((const unsigned int*)ei, E);
    count_k<<<(E + 255) / 256, 256>>>(ei, E);
    scanA_k<<<nb, 256>>>(N);
    scanB_k<<<1, 256>>>(nb);
    scanC_k<<<nb, 256>>>(N, E);
    scatter_k<<<(E + 255) / 256, 256>>>(ei, ew, E);

    // weight splits (fp32 -> bf16 hi|lo)
    split_k<<<((size_t)L * H * 64 + 255) / 256, 256>>>(wL, wls, L * H);     // W row-major
    split_k<<<((size_t)3 * H * 64 + 255) / 256, 256>>>(w_ih, wihs, 3 * H);
    split_k<<<((size_t)3 * H * 64 + 255) / 256, 256>>>(w_hh, whhs, 3 * H);
    split_k<<<((size_t)N * 64 + 255) / 256, 256>>>(h0, hs, N);

    // combined weights: Wc[l][c,k] = sum_j w_ih[c,j] * W[l][k,j]  (so gi = agg_h @ Wc^T)
    {
        dim3 gw((768 + 127) / 128, 2, 1);   // M=768, Ntot=256
        for (int l = 0; l < L; l++) {
            gemm_mma<<<gw, 256, GEMM_SMEM>>>(wihs, wihs,
                                             wls + (size_t)l * H * 512, wls + (size_t)l * H * 512,
                                             nullptr, nullptr, wcf, wcf, 3 * H, H);
            split_k<<<(768 * 64 + 255) / 256, 256>>>(wcf, wcs + (size_t)l * 768 * 512, 3 * H);
        }
    }

    float* hc = h0;
    float* hx = h1;
    int mtiles = (N + 127) / 128;
    dim3 gg_(mtiles, 6, 2);     // Ntot = 768, z: 0 = gi (combined W), 1 = gh

    for (int l = 0; l < L; l++) {
        aggregate_k<<<((size_t)N * 32 + 255) / 256, 256>>>(hc, as, N);
        gemm_mma<<<gg_, 256, GEMM_SMEM>>>(as, hs,
                                          wcs + (size_t)l * 768 * 512, whhs,
                                          b_ih, b_hh, gi, gh, N, 3 * H);
        gru_k<<<((size_t)N * (H / 4) + 255) / 256, 256>>>(gi, gh, hc, hx, hs, N);
        float* t = hc; hc = hx; hx = t;
    }
    final_k<<<((size_t)N * 32 + 255) / 256, 256>>>(hc, fcw, fcb, (float*)d_out, N);
}